// round 2
// baseline (speedup 1.0000x reference)
#include <cuda_runtime.h>

// NonLocalBlock: x[4,256,64,64] fp32, C=256, N=4096 tokens per batch.
// Reference's .reshape(b,n,c) on the NCHW conv output is a raw view:
// the [256,4096] row-major conv result is bit-identical to the [4096,256]
// row-major Q/K/V matrix. So:
//   Yq = Wq@X + bq   (X = x[b] as [256,4096])        -> Q = view [4096,256]
//   S  = Q @ K^T     [4096,4096], softmax rows
//   A  = S @ V       [4096,256]  -> view [256,4096]
//   out = Wu@A + bu + x  (residual)
// Exact fp32 math; inner product uses packed fma.rn.f32x2 (FFMA2) to halve
// FMA-pipe issue count on sm_103a.

#define BM 128
#define BN 128
#define BK 8

// Scratch (allocation-free rule: __device__ globals)
__device__ float g_q[4L * 4096 * 256];
__device__ float g_k[4L * 4096 * 256];
__device__ float g_v[4L * 4096 * 256];
__device__ float g_p[4L * 4096 * 4096];   // 256 MB score/prob matrix
__device__ float g_a[4L * 4096 * 256];

// ---- packed f32x2 helpers (Blackwell sm_103a) ----
__device__ __forceinline__ unsigned long long pack_dup(float a) {
    unsigned long long r;
    asm("mov.b64 %0, {%1, %1};" : "=l"(r) : "f"(a));
    return r;
}
__device__ __forceinline__ void fma2(unsigned long long& acc,
                                     unsigned long long a,
                                     unsigned long long b) {
    asm("fma.rn.f32x2 %0, %1, %2, %0;" : "+l"(acc) : "l"(a), "l"(b));
}
__device__ __forceinline__ float2 unpack2(unsigned long long v) {
    float2 r;
    asm("mov.b64 {%0, %1}, %2;" : "=f"(r.x), "=f"(r.y) : "l"(v));
    return r;
}

// Generic batched tiled SGEMM: C[M,N] = A[M,K] * B (+bias +residual)
// TRANSB=false: B is [K,N] row-major (ldb = row stride)
// TRANSB=true : B is [N,K] row-major, used as B^T
// EPI: 0 = plain, 1 = +bias[m], 2 = +bias[m] +resid (same layout as C)
template <bool TRANSB, int EPI>
__global__ __launch_bounds__(256, 2) void gemm_k(
    const float* __restrict__ Ag, long long sA, int lda,
    const float* __restrict__ Bg, long long sB, int ldb,
    float* __restrict__ Cg, long long sC, int ldc,
    int K,
    const float* __restrict__ bias,
    const float* __restrict__ resid, long long sR)
{
    __shared__ float As[BK][BM];
    __shared__ float Bs[BK][BN];

    const int batch = blockIdx.z;
    const float* A = Ag + (long long)batch * sA;
    const float* B = Bg + (long long)batch * sB;
    float* C = Cg + (long long)batch * sC;

    const int bm = blockIdx.y * BM;
    const int bn = blockIdx.x * BN;
    const int tid = threadIdx.x;

    // 16x16 thread grid, each thread an 8x8 microtile (acc packed 8x4 f32x2)
    const int tx = tid & 15;
    const int ty = tid >> 4;
    const int m0 = ty * 8;
    const int n0 = tx * 8;

    unsigned long long acc[8][4];
#pragma unroll
    for (int i = 0; i < 8; i++)
#pragma unroll
        for (int j = 0; j < 4; j++) acc[i][j] = 0ULL;

    // load mapping
    const int arow = tid >> 1;          // 0..127
    const int acg  = (tid & 1) * 4;     // 0 or 4
    const int brow = tid >> 5;          // 0..7   (no-trans B)
    const int bcol = (tid & 31) * 4;    // 0..124 (no-trans B)

    const float* Ab = A + (long long)bm * lda;
    const float* Bb = TRANSB ? (B + (long long)bn * ldb) : (B + bn);

    for (int kk = 0; kk < K; kk += BK) {
        // prefetch into registers
        float4 av = *(const float4*)(Ab + (long long)arow * lda + kk + acg);
        float4 bv;
        if (TRANSB) {
            bv = *(const float4*)(Bb + (long long)arow * ldb + kk + acg);
        } else {
            bv = *(const float4*)(Bb + (long long)(kk + brow) * ldb + bcol);
        }
        __syncthreads();  // previous tile fully consumed before overwrite
        As[acg + 0][arow] = av.x;
        As[acg + 1][arow] = av.y;
        As[acg + 2][arow] = av.z;
        As[acg + 3][arow] = av.w;
        if (TRANSB) {
            Bs[acg + 0][arow] = bv.x;
            Bs[acg + 1][arow] = bv.y;
            Bs[acg + 2][arow] = bv.z;
            Bs[acg + 3][arow] = bv.w;
        } else {
            *(float4*)&Bs[brow][bcol] = bv;
        }
        __syncthreads();

#pragma unroll
        for (int k = 0; k < BK; k++) {
            float a[8];
            *(float4*)(a)     = *(const float4*)&As[k][m0];
            *(float4*)(a + 4) = *(const float4*)&As[k][m0 + 4];
            // b pairs come directly from 128-bit shared loads
            ulonglong2 bq0 = *(const ulonglong2*)&Bs[k][n0];
            ulonglong2 bq1 = *(const ulonglong2*)&Bs[k][n0 + 4];
            unsigned long long b2[4] = {bq0.x, bq0.y, bq1.x, bq1.y};
            unsigned long long a2[8];
#pragma unroll
            for (int i = 0; i < 8; i++) a2[i] = pack_dup(a[i]);
#pragma unroll
            for (int i = 0; i < 8; i++)
#pragma unroll
                for (int j = 0; j < 4; j++)
                    fma2(acc[i][j], a2[i], b2[j]);
        }
    }

    // epilogue
#pragma unroll
    for (int i = 0; i < 8; i++) {
        const int m = bm + m0 + i;
        const float badd = (EPI >= 1) ? bias[m] : 0.f;
#pragma unroll
        for (int jp = 0; jp < 4; jp += 2) {
            const int n = bn + n0 + jp * 2;
            float2 p0 = unpack2(acc[i][jp]);
            float2 p1 = unpack2(acc[i][jp + 1]);
            float4 v;
            v.x = p0.x + badd;
            v.y = p0.y + badd;
            v.z = p1.x + badd;
            v.w = p1.y + badd;
            if (EPI == 2) {
                const float4 r = *(const float4*)(resid + (long long)batch * sR +
                                                  (long long)m * ldc + n);
                v.x += r.x; v.y += r.y; v.z += r.z; v.w += r.w;
            }
            *(float4*)(C + (long long)m * ldc + n) = v;
        }
    }
}

// Row softmax over S rows of length 4096. One block (256 thr) per row.
__global__ __launch_bounds__(256) void softmax_k(float* __restrict__ S)
{
    const long long row = (long long)blockIdx.y * 4096 + blockIdx.x;
    float* p = S + row * 4096;
    const int tid = threadIdx.x;

    float v[16];
    float mx = -1e30f;
#pragma unroll
    for (int i = 0; i < 16; i++) {
        v[i] = p[tid + i * 256];
        mx = fmaxf(mx, v[i]);
    }

    __shared__ float red[256];
    red[tid] = mx;
    __syncthreads();
    for (int s = 128; s > 0; s >>= 1) {
        if (tid < s) red[tid] = fmaxf(red[tid], red[tid + s]);
        __syncthreads();
    }
    mx = red[0];
    __syncthreads();

    float sum = 0.f;
#pragma unroll
    for (int i = 0; i < 16; i++) {
        v[i] = __expf(v[i] - mx);
        sum += v[i];
    }
    red[tid] = sum;
    __syncthreads();
    for (int s = 128; s > 0; s >>= 1) {
        if (tid < s) red[tid] += red[tid + s];
        __syncthreads();
    }
    const float inv = 1.f / red[0];
#pragma unroll
    for (int i = 0; i < 16; i++)
        p[tid + i * 256] = v[i] * inv;
}

extern "C" void kernel_launch(void* const* d_in, const int* in_sizes, int n_in,
                              void* d_out, int out_size)
{
    const float* x  = (const float*)d_in[0];
    const float* Wq = (const float*)d_in[1];
    const float* bq = (const float*)d_in[2];
    const float* Wk = (const float*)d_in[3];
    const float* bk = (const float*)d_in[4];
    const float* Wv = (const float*)d_in[5];
    const float* bv = (const float*)d_in[6];
    const float* Wu = (const float*)d_in[7];
    const float* bu = (const float*)d_in[8];
    float* out = (float*)d_out;

    float *q, *k, *v, *p, *a;
    cudaGetSymbolAddress((void**)&q, g_q);
    cudaGetSymbolAddress((void**)&k, g_k);
    cudaGetSymbolAddress((void**)&v, g_v);
    cudaGetSymbolAddress((void**)&p, g_p);
    cudaGetSymbolAddress((void**)&a, g_a);

    const long long BXS = 256LL * 4096;       // per-batch x / qkv stride (1M)
    const long long PS  = 4096LL * 4096;      // per-batch score stride (16M)

    // QKV projections: C[256,4096] = W[256,256] @ X[256,4096] + b
    gemm_k<false, 1><<<dim3(32, 2, 4), 256>>>(Wq, 0, 256, x, BXS, 4096,
                                              q, BXS, 4096, 256, bq, nullptr, 0);
    gemm_k<false, 1><<<dim3(32, 2, 4), 256>>>(Wk, 0, 256, x, BXS, 4096,
                                              k, BXS, 4096, 256, bk, nullptr, 0);
    gemm_k<false, 1><<<dim3(32, 2, 4), 256>>>(Wv, 0, 256, x, BXS, 4096,
                                              v, BXS, 4096, 256, bv, nullptr, 0);

    // S = Q @ K^T : [4096,4096], K-inner = 256 (NT)
    gemm_k<true, 0><<<dim3(32, 32, 4), 256>>>(q, BXS, 256, k, BXS, 256,
                                              p, PS, 4096, 256, nullptr, nullptr, 0);

    // row softmax
    softmax_k<<<dim3(4096, 4), 256>>>(p);

    // A = P @ V : [4096,256], K-inner = 4096 (NN)
    gemm_k<false, 0><<<dim3(2, 32, 4), 256>>>(p, PS, 4096, v, BXS, 256,
                                              a, BXS, 256, 4096, nullptr, nullptr, 0);

    // out = Wu @ A_view[256,4096] + bu + x  (residual)
    gemm_k<false, 2><<<dim3(32, 2, 4), 256>>>(Wu, 0, 256, a, BXS, 4096,
                                              out, BXS, 4096, 256, bu, x, BXS);
}

// round 10
// speedup vs baseline: 1.7836x; 1.7836x over previous
#include <cuda_runtime.h>
#include <cuda_bf16.h>
#include <cstdint>

typedef __nv_bfloat16 bf16;
typedef unsigned int u32;
typedef unsigned long long u64;

// ============ scratch (allocation-free rule: __device__ globals) ============
__device__ float g_s  [4L*4096*4096];          // fp32 scores
__device__ bf16  g_phi[4L*4096*4096];          // softmax probs hi
__device__ bf16  g_plo[4L*4096*4096];          // softmax probs lo
#define QSZ (4L*4096*256)
__device__ bf16 g_qhi[QSZ], g_qlo[QSZ];
__device__ bf16 g_khi[QSZ], g_klo[QSZ];
__device__ bf16 g_vhi[QSZ], g_vlo[QSZ];
__device__ bf16 g_vthi[QSZ], g_vtlo[QSZ];      // V^T  [256,4096]/batch
__device__ bf16 g_ahi[QSZ], g_alo[QSZ];        // attn out (flat NCHW view)
__device__ bf16 g_athi[QSZ], g_atlo[QSZ];      // attn^T
__device__ bf16 g_xthi[QSZ], g_xtlo[QSZ];      // x^T  [4096,256]/batch
__device__ bf16 g_whi[4*256*256], g_wlo[4*256*256];

// ============ helpers ============
__device__ __forceinline__ u32 smem_u32(const void* p) {
    u32 a;
    asm("{ .reg .u64 t; cvta.to.shared.u64 t, %1; cvt.u32.u64 %0, t; }"
        : "=r"(a) : "l"(p));
    return a;
}
__device__ __forceinline__ void ldm4(u32& r0, u32& r1, u32& r2, u32& r3, u32 addr) {
    asm volatile("ldmatrix.sync.aligned.m8n8.x4.shared.b16 {%0,%1,%2,%3}, [%4];"
                 : "=r"(r0), "=r"(r1), "=r"(r2), "=r"(r3) : "r"(addr));
}
__device__ __forceinline__ void mma16816(float* c, const u32* a, u32 b0, u32 b1) {
    asm volatile(
        "mma.sync.aligned.m16n8k16.row.col.f32.bf16.bf16.f32 "
        "{%0,%1,%2,%3}, {%4,%5,%6,%7}, {%8,%9}, {%0,%1,%2,%3};"
        : "+f"(c[0]), "+f"(c[1]), "+f"(c[2]), "+f"(c[3])
        : "r"(a[0]), "r"(a[1]), "r"(a[2]), "r"(a[3]), "r"(b0), "r"(b1));
}

#define SPAD 40   // smem row stride in halves (32 data + 8 pad)

// ============ NT split-bf16 HMMA GEMM: C[M,N] = A[M,K] * B[N,K]^T ============
// A,B bf16 hi/lo, K-major. 128x128 CTA tile, BK=32, 256 thr, 8 warps (2m x 4n),
// warp tile 64x32. 3-term: ahi*bhi + ahi*blo + alo*bhi, fp32 accum.
// EPI 0: fp32 C. 1: bf16 hi/lo C + bias[m]. 2: fp32 C + bias[m] + resid. 3: bf16 hi/lo C.
template <int EPI>
__global__ __launch_bounds__(256, 1) void gemm_mma(
    const bf16* __restrict__ Ahi, const bf16* __restrict__ Alo, long long sA, int lda,
    const bf16* __restrict__ Bhi, const bf16* __restrict__ Blo, long long sB, int ldb,
    float* __restrict__ Cf, bf16* __restrict__ Chi, bf16* __restrict__ Clo,
    long long sC, int ldc, int K,
    const float* __restrict__ bias, const float* __restrict__ resid)
{
    __shared__ __align__(16) bf16 sAh[128 * SPAD], sAl[128 * SPAD];
    __shared__ __align__(16) bf16 sBh[128 * SPAD], sBl[128 * SPAD];

    const int tid = threadIdx.x;
    const int lane = tid & 31;
    const int wid = tid >> 5;
    const int wm = wid >> 2;        // 0..1
    const int wn = wid & 3;         // 0..3
    const int batch = blockIdx.z;
    const int bm = blockIdx.y * 128;
    const int bn = blockIdx.x * 128;

    const bf16* Ah = Ahi + (long long)batch * sA;
    const bf16* Al = Alo + (long long)batch * sA;
    const bf16* Bh = Bhi + (long long)batch * sB;
    const bf16* Bl = Blo + (long long)batch * sB;

    float acc[4][4][4];
#pragma unroll
    for (int i = 0; i < 4; i++)
#pragma unroll
        for (int j = 0; j < 4; j++)
#pragma unroll
            for (int r = 0; r < 4; r++) acc[i][j][r] = 0.f;

    const u32 sbAh = smem_u32(sAh), sbAl = smem_u32(sAl);
    const u32 sbBh = smem_u32(sBh), sbBl = smem_u32(sBl);

    // ldmatrix per-thread offsets (in halves)
    const int sub_lo = (lane >> 3) & 1;
    const int sub_hi = (lane >> 4) & 1;
    const int t7 = lane & 7;
    // A: row-half from sub_lo, k-half from sub_hi. B: row-half from sub_hi, k-half from sub_lo.

    for (int kk = 0; kk < K; kk += 32) {
        // gmem -> regs
        uint4 rAh[2], rAl[2], rBh[2], rBl[2];
        int rows[2], segs[2];
#pragma unroll
        for (int i = 0; i < 2; i++) {
            const int idx = tid + i * 256;         // 0..511
            rows[i] = idx >> 2;
            segs[i] = (idx & 3) * 8;
            const long long ga = (long long)(bm + rows[i]) * lda + kk + segs[i];
            const long long gb = (long long)(bn + rows[i]) * ldb + kk + segs[i];
            rAh[i] = *(const uint4*)(Ah + ga);
            rAl[i] = *(const uint4*)(Al + ga);
            rBh[i] = *(const uint4*)(Bh + gb);
            rBl[i] = *(const uint4*)(Bl + gb);
        }
        __syncthreads();   // previous tile fully consumed
#pragma unroll
        for (int i = 0; i < 2; i++) {
            const int so = rows[i] * SPAD + segs[i];
            *(uint4*)(sAh + so) = rAh[i];
            *(uint4*)(sAl + so) = rAl[i];
            *(uint4*)(sBh + so) = rBh[i];
            *(uint4*)(sBl + so) = rBl[i];
        }
        __syncthreads();

#pragma unroll
        for (int ks = 0; ks < 32; ks += 16) {
            u32 ah[4][4], al[4][4], bh[4][2], bl[4][2];
            const int ka = ks + (sub_hi << 3);
            const int kb = ks + (sub_lo << 3);
#pragma unroll
            for (int mt = 0; mt < 4; mt++) {
                const int m = wm * 64 + mt * 16 + (sub_lo << 3) + t7;
                const u32 off = (u32)(m * SPAD + ka) * 2;
                ldm4(ah[mt][0], ah[mt][1], ah[mt][2], ah[mt][3], sbAh + off);
                ldm4(al[mt][0], al[mt][1], al[mt][2], al[mt][3], sbAl + off);
            }
#pragma unroll
            for (int nt2 = 0; nt2 < 2; nt2++) {
                const int n = wn * 32 + nt2 * 16 + (sub_hi << 3) + t7;
                const u32 off = (u32)(n * SPAD + kb) * 2;
                u32 r0, r1, r2, r3;
                ldm4(r0, r1, r2, r3, sbBh + off);
                bh[2 * nt2][0] = r0; bh[2 * nt2][1] = r1;
                bh[2 * nt2 + 1][0] = r2; bh[2 * nt2 + 1][1] = r3;
                ldm4(r0, r1, r2, r3, sbBl + off);
                bl[2 * nt2][0] = r0; bl[2 * nt2][1] = r1;
                bl[2 * nt2 + 1][0] = r2; bl[2 * nt2 + 1][1] = r3;
            }
#pragma unroll
            for (int mt = 0; mt < 4; mt++)
#pragma unroll
                for (int nt = 0; nt < 4; nt++) {
                    mma16816(acc[mt][nt], ah[mt], bh[nt][0], bh[nt][1]);
                    mma16816(acc[mt][nt], ah[mt], bl[nt][0], bl[nt][1]);
                    mma16816(acc[mt][nt], al[mt], bh[nt][0], bh[nt][1]);
                }
        }
        __syncthreads();
    }

    // ============ epilogue ============
    const int gid = lane >> 2;
    const int tq = lane & 3;
#pragma unroll
    for (int mt = 0; mt < 4; mt++) {
#pragma unroll
        for (int nt = 0; nt < 4; nt++) {
            const float* c = acc[mt][nt];
            const int col = bn + wn * 32 + nt * 8 + tq * 2;
#pragma unroll
            for (int h = 0; h < 2; h++) {
                const int row = bm + wm * 64 + mt * 16 + gid + h * 8;
                const float v0 = c[2 * h + 0];
                const float v1 = c[2 * h + 1];
                if (EPI == 0) {
                    float2 w; w.x = v0; w.y = v1;
                    *(float2*)(Cf + (long long)batch * sC + (long long)row * ldc + col) = w;
                } else if (EPI == 2) {
                    const float bi = bias[row];
                    const float2 r = *(const float2*)(resid + (long long)batch * sC +
                                                      (long long)row * ldc + col);
                    float2 w; w.x = v0 + bi + r.x; w.y = v1 + bi + r.y;
                    *(float2*)(Cf + (long long)batch * sC + (long long)row * ldc + col) = w;
                } else {
                    const float bi = (EPI == 1) ? bias[row] : 0.f;
                    const float u0 = v0 + bi, u1 = v1 + bi;
                    const bf16 h0 = __float2bfloat16(u0);
                    const bf16 h1 = __float2bfloat16(u1);
                    const bf16 l0 = __float2bfloat16(u0 - __bfloat162float(h0));
                    const bf16 l1 = __float2bfloat16(u1 - __bfloat162float(h1));
                    __nv_bfloat162 hp; hp.x = h0; hp.y = h1;
                    __nv_bfloat162 lp; lp.x = l0; lp.y = l1;
                    *(__nv_bfloat162*)(Chi + (long long)batch * sC + (long long)row * ldc + col) = hp;
                    *(__nv_bfloat162*)(Clo + (long long)batch * sC + (long long)row * ldc + col) = lp;
                }
            }
        }
    }
}

// ============ softmax: fp32 row in, bf16 hi/lo out ============
__global__ __launch_bounds__(256) void softmax_k(
    const float* __restrict__ S, bf16* __restrict__ Phi, bf16* __restrict__ Plo)
{
    const long long row = (long long)blockIdx.y * 4096 + blockIdx.x;
    const float* p = S + row * 4096;
    bf16* oh = Phi + row * 4096;
    bf16* ol = Plo + row * 4096;
    const int tid = threadIdx.x;

    float v[16];
    float mx = -1e30f;
#pragma unroll
    for (int i = 0; i < 16; i++) {
        v[i] = p[tid + i * 256];
        mx = fmaxf(mx, v[i]);
    }
    __shared__ float red[256];
    red[tid] = mx;
    __syncthreads();
    for (int s = 128; s > 0; s >>= 1) {
        if (tid < s) red[tid] = fmaxf(red[tid], red[tid + s]);
        __syncthreads();
    }
    mx = red[0];
    __syncthreads();
    float sum = 0.f;
#pragma unroll
    for (int i = 0; i < 16; i++) {
        v[i] = __expf(v[i] - mx);
        sum += v[i];
    }
    red[tid] = sum;
    __syncthreads();
    for (int s = 128; s > 0; s >>= 1) {
        if (tid < s) red[tid] += red[tid + s];
        __syncthreads();
    }
    const float inv = 1.f / red[0];
#pragma unroll
    for (int i = 0; i < 16; i++) {
        const float pv = v[i] * inv;
        const bf16 h = __float2bfloat16(pv);
        oh[tid + i * 256] = h;
        ol[tid + i * 256] = __float2bfloat16(pv - __bfloat162float(h));
    }
}

// ============ transposes ============
__global__ void transpose_bf(const bf16* __restrict__ ih, const bf16* __restrict__ il,
                             bf16* __restrict__ oh, bf16* __restrict__ ol, int R, int C)
{
    __shared__ bf16 th[32][33], tl[32][33];
    const long long base = (long long)blockIdx.z * R * C;
    const int i0 = blockIdx.y * 32, j0 = blockIdx.x * 32;
    const int tx = threadIdx.x, ty = threadIdx.y;
#pragma unroll
    for (int k = 0; k < 4; k++) {
        const int r = ty + k * 8;
        th[r][tx] = ih[base + (long long)(i0 + r) * C + j0 + tx];
        tl[r][tx] = il[base + (long long)(i0 + r) * C + j0 + tx];
    }
    __syncthreads();
#pragma unroll
    for (int k = 0; k < 4; k++) {
        const int r = ty + k * 8;
        oh[base + (long long)(j0 + r) * R + i0 + tx] = th[tx][r];
        ol[base + (long long)(j0 + r) * R + i0 + tx] = tl[tx][r];
    }
}

__global__ void transpose_cvt(const float* __restrict__ in,
                              bf16* __restrict__ oh, bf16* __restrict__ ol, int R, int C)
{
    __shared__ float t[32][33];
    const long long base = (long long)blockIdx.z * R * C;
    const int i0 = blockIdx.y * 32, j0 = blockIdx.x * 32;
    const int tx = threadIdx.x, ty = threadIdx.y;
#pragma unroll
    for (int k = 0; k < 4; k++) {
        const int r = ty + k * 8;
        t[r][tx] = in[base + (long long)(i0 + r) * C + j0 + tx];
    }
    __syncthreads();
#pragma unroll
    for (int k = 0; k < 4; k++) {
        const int r = ty + k * 8;
        const float v = t[tx][r];
        const bf16 h = __float2bfloat16(v);
        oh[base + (long long)(j0 + r) * R + i0 + tx] = h;
        ol[base + (long long)(j0 + r) * R + i0 + tx] = __float2bfloat16(v - __bfloat162float(h));
    }
}

__global__ void cvt_k(const float* __restrict__ in, bf16* __restrict__ oh,
                      bf16* __restrict__ ol, int n)
{
    const int i = blockIdx.x * 256 + threadIdx.x;
    if (i < n) {
        const float v = in[i];
        const bf16 h = __float2bfloat16(v);
        oh[i] = h;
        ol[i] = __float2bfloat16(v - __bfloat162float(h));
    }
}

// ============ launch ============
extern "C" void kernel_launch(void* const* d_in, const int* in_sizes, int n_in,
                              void* d_out, int out_size)
{
    const float* x  = (const float*)d_in[0];
    const float* Wq = (const float*)d_in[1];
    const float* bq = (const float*)d_in[2];
    const float* Wk = (const float*)d_in[3];
    const float* bk = (const float*)d_in[4];
    const float* Wv = (const float*)d_in[5];
    const float* bv = (const float*)d_in[6];
    const float* Wu = (const float*)d_in[7];
    const float* bu = (const float*)d_in[8];
    float* out = (float*)d_out;

    float* s;
    bf16 *phi, *plo, *qhi, *qlo, *khi, *klo, *vhi, *vlo, *vthi, *vtlo;
    bf16 *ahi, *alo, *athi, *atlo, *xthi, *xtlo, *whi, *wlo;
    cudaGetSymbolAddress((void**)&s,    g_s);
    cudaGetSymbolAddress((void**)&phi,  g_phi);
    cudaGetSymbolAddress((void**)&plo,  g_plo);
    cudaGetSymbolAddress((void**)&qhi,  g_qhi);
    cudaGetSymbolAddress((void**)&qlo,  g_qlo);
    cudaGetSymbolAddress((void**)&khi,  g_khi);
    cudaGetSymbolAddress((void**)&klo,  g_klo);
    cudaGetSymbolAddress((void**)&vhi,  g_vhi);
    cudaGetSymbolAddress((void**)&vlo,  g_vlo);
    cudaGetSymbolAddress((void**)&vthi, g_vthi);
    cudaGetSymbolAddress((void**)&vtlo, g_vtlo);
    cudaGetSymbolAddress((void**)&ahi,  g_ahi);
    cudaGetSymbolAddress((void**)&alo,  g_alo);
    cudaGetSymbolAddress((void**)&athi, g_athi);
    cudaGetSymbolAddress((void**)&atlo, g_atlo);
    cudaGetSymbolAddress((void**)&xthi, g_xthi);
    cudaGetSymbolAddress((void**)&xtlo, g_xtlo);
    cudaGetSymbolAddress((void**)&whi,  g_whi);
    cudaGetSymbolAddress((void**)&wlo,  g_wlo);

    const long long BXS = 256LL * 4096;   // 1M elems/batch
    const long long PS  = 4096LL * 4096;  // 16M elems/batch

    // weights -> bf16 hi/lo
    cvt_k<<<256, 256>>>(Wq, whi + 0 * 65536, wlo + 0 * 65536, 65536);
    cvt_k<<<256, 256>>>(Wk, whi + 1 * 65536, wlo + 1 * 65536, 65536);
    cvt_k<<<256, 256>>>(Wv, whi + 2 * 65536, wlo + 2 * 65536, 65536);
    cvt_k<<<256, 256>>>(Wu, whi + 3 * 65536, wlo + 3 * 65536, 65536);
    // x^T -> bf16 hi/lo  (viewed [256,4096] -> [4096,256])
    transpose_cvt<<<dim3(128, 8, 4), dim3(32, 8)>>>(x, xthi, xtlo, 256, 4096);

    // projections: C[c,p] = W[c,:]·xT[p,:] + b  (M=256,N=4096,K=256) -> bf16 hi/lo
    gemm_mma<1><<<dim3(32, 2, 4), 256>>>(
        whi + 0 * 65536, wlo + 0 * 65536, 0, 256, xthi, xtlo, BXS, 256,
        nullptr, qhi, qlo, BXS, 4096, 256, bq, nullptr);
    gemm_mma<1><<<dim3(32, 2, 4), 256>>>(
        whi + 1 * 65536, wlo + 1 * 65536, 0, 256, xthi, xtlo, BXS, 256,
        nullptr, khi, klo, BXS, 4096, 256, bk, nullptr);
    gemm_mma<1><<<dim3(32, 2, 4), 256>>>(
        whi + 2 * 65536, wlo + 2 * 65536, 0, 256, xthi, xtlo, BXS, 256,
        nullptr, vhi, vlo, BXS, 4096, 256, bv, nullptr);

    // V^T (view [4096,256] -> [256,4096])
    transpose_bf<<<dim3(8, 128, 4), dim3(32, 8)>>>(vhi, vlo, vthi, vtlo, 4096, 256);

    // S = Q·K^T  (M=N=4096, K=256), fp32 out
    gemm_mma<0><<<dim3(32, 32, 4), 256>>>(
        qhi, qlo, BXS, 256, khi, klo, BXS, 256,
        s, nullptr, nullptr, PS, 4096, 256, nullptr, nullptr);

    // softmax -> P hi/lo
    softmax_k<<<dim3(4096, 4), 256>>>(s, phi, plo);

    // attn = P·V  via  A=P [4096,4096], B=V^T [256,4096]  (M=4096,N=256,K=4096)
    gemm_mma<3><<<dim3(2, 32, 4), 256>>>(
        phi, plo, PS, 4096, vthi, vtlo, BXS, 4096,
        nullptr, ahi, alo, BXS, 256, 4096, nullptr, nullptr);

    // attn^T (view [256,4096] -> [4096,256])
    transpose_bf<<<dim3(128, 8, 4), dim3(32, 8)>>>(ahi, alo, athi, atlo, 256, 4096);

    // out = Wu·attn_view + bu + x  (M=256,N=4096,K=256), fp32 + residual
    gemm_mma<2><<<dim3(32, 2, 4), 256>>>(
        whi + 3 * 65536, wlo + 3 * 65536, 0, 256, athi, atlo, BXS, 256,
        out, nullptr, nullptr, BXS, 4096, 256, bu, x);
}